// round 15
// baseline (speedup 1.0000x reference)
#include <cuda_runtime.h>
#include <math.h>

#define NPLANES 24
#define H0 1280
#define W0 1280

// ---------------------------------------------------------------------------
// Scratch
// ---------------------------------------------------------------------------
__device__ float g_pyr1[NPLANES * 640 * 640];
__device__ float g_pyr2[NPLANES * 320 * 320];
__device__ float g_pyr3[NPLANES * 160 * 160];
__device__ float g_t80[3 * NPLANES * 80 * 80];   // filter results at 80 level

__device__ __forceinline__ int refl101(int i, int n) {
    if (i < 0) i = -i;
    if (i >= n) i = 2 * n - 2 - i;
    return i;
}

// ---------------------------------------------------------------------------
// f32x2 packed helpers (Blackwell)
// ---------------------------------------------------------------------------
typedef unsigned long long ull;
__device__ __forceinline__ ull pk2(float a, float b) {
    ull r;
    asm("mov.b64 %0, {%1, %2};" : "=l"(r)
        : "r"(__float_as_uint(a)), "r"(__float_as_uint(b)));
    return r;
}
__device__ __forceinline__ void upk2(ull v, float& a, float& b) {
    unsigned int lo, hi;
    asm("mov.b64 {%0, %1}, %2;" : "=r"(lo), "=r"(hi) : "l"(v));
    a = __uint_as_float(lo);
    b = __uint_as_float(hi);
}
__device__ __forceinline__ ull fma2(ull a, ull b, ull c) {
    ull r;
    asm("fma.rn.f32x2 %0, %1, %2, %3;" : "=l"(r) : "l"(a), "l"(b), "l"(c));
    return r;
}
__device__ __forceinline__ ull mul2(ull a, ull b) {
    ull r;
    asm("mul.rn.f32x2 %0, %1, %2;" : "=l"(r) : "l"(a), "l"(b));
    return r;
}

// ---------------------------------------------------------------------------
// pyrDown, 4x4 outputs/thread (proven in R8/R10/R12).
// ---------------------------------------------------------------------------
__global__ void __launch_bounds__(256)
pyrdown16_kernel(const float* __restrict__ src,
                 float* __restrict__ dst, int H, int W) {
    const int Ho = H >> 1, Wo = W >> 1;
    const int Wq = Wo >> 2, Hq = Ho >> 2;
    const int total = NPLANES * Hq * Wq;
    int idx = blockIdx.x * blockDim.x + threadIdx.x;
    if (idx >= total) return;
    int wq = idx % Wq;
    int t  = idx / Wq;
    int hq = t % Hq;
    int p  = t / Hq;
    int ho0 = hq << 2, wo0 = wq << 2;

    const float* s = src + (size_t)p * H * W;
    const float kk[5] = {0.0625f, 0.25f, 0.375f, 0.25f, 0.0625f};
    float* dbase = dst + (size_t)p * Ho * Wo;

    bool interior = (ho0 >= 1) && (2 * ho0 + 8 <= H - 1) &&
                    (wq >= 1) && (8 * wq + 11 <= W - 1);
    if (interior) {
        float hs[11][4];
        const float* rowp = s + (size_t)(2 * ho0 - 2) * W + (8 * wq - 4);
#pragma unroll
        for (int r = 0; r < 11; r++, rowp += W) {
            const float4* r4 = (const float4*)rowp;
            float4 A = r4[0], Bv = r4[1], C = r4[2], D = r4[3];
            float v[16] = {A.x, A.y, A.z, A.w, Bv.x, Bv.y, Bv.z, Bv.w,
                           C.x, C.y, C.z, C.w, D.x, D.y, D.z, D.w};
#pragma unroll
            for (int o = 0; o < 4; o++)
                hs[r][o] = 0.0625f * (v[2 * o + 2] + v[2 * o + 6])
                         + 0.25f   * (v[2 * o + 3] + v[2 * o + 5])
                         + 0.375f  *  v[2 * o + 4];
        }
#pragma unroll
        for (int ry = 0; ry < 4; ry++) {
            float4 o4;
            float* acc = (float*)&o4;
#pragma unroll
            for (int o = 0; o < 4; o++) {
                float a = 0.f;
#pragma unroll
                for (int dy = 0; dy < 5; dy++)
                    a += kk[dy] * hs[2 * ry + dy][o];
                acc[o] = a;
            }
            *(float4*)(dbase + (size_t)(ho0 + ry) * Wo + wo0) = o4;
        }
    } else {
#pragma unroll
        for (int ry = 0; ry < 4; ry++) {
            int ho = ho0 + ry;
            float4 o4;
            float* acc = (float*)&o4;
#pragma unroll
            for (int o = 0; o < 4; o++) {
                int wo = wo0 + o;
                float a = 0.f;
#pragma unroll
                for (int dy = 0; dy < 5; dy++) {
                    int y = refl101(2 * ho + dy - 2, H);
                    const float* row = s + (size_t)y * W;
                    float r2 = 0.f;
#pragma unroll
                    for (int dx = 0; dx < 5; dx++)
                        r2 += kk[dx] * row[refl101(2 * wo + dx - 2, W)];
                    a += kk[dy] * r2;
                }
                acc[o] = a;
            }
            *(float4*)(dbase + (size_t)ho * Wo + wo0) = o4;
        }
    }
}

// ---------------------------------------------------------------------------
// Generic-pointer per-plane helpers (smem or gmem)
// ---------------------------------------------------------------------------
__device__ void pyrdown_plane(const float* s, float* d, int N, int tid, int nt) {
    const int No = N >> 1;
    const int total = No * No;
    const float kk[5] = {0.0625f, 0.25f, 0.375f, 0.25f, 0.0625f};
    for (int idx = tid; idx < total; idx += nt) {
        int wo = idx % No, ho = idx / No;
        float acc = 0.f;
#pragma unroll
        for (int dy = 0; dy < 5; dy++) {
            int y = refl101(2 * ho + dy - 2, N);
            const float* row = s + y * N;
            float r = 0.f;
#pragma unroll
            for (int dx = 0; dx < 5; dx++)
                r += kk[dx] * row[refl101(2 * wo + dx - 2, N)];
            acc += kk[dy] * r;
        }
        d[idx] = acc;
    }
}

__device__ void up2_plane(const float* s, float* d, int N, int tid, int nt) {
    const int No = 2 * N;
    const int total = No * No;
    for (int idx = tid; idx < total; idx += nt) {
        int wo = idx % No, ho = idx / No;
        int iy = (ho >> 1) + (ho & 1) - 1;
        float fy = (ho & 1) ? 0.25f : 0.75f;
        int y0 = max(iy, 0), y1 = min(iy + 1, N - 1);
        int ix = (wo >> 1) + (wo & 1) - 1;
        float fx = (wo & 1) ? 0.25f : 0.75f;
        int x0 = max(ix, 0), x1 = min(ix + 1, N - 1);
        float v00 = s[y0 * N + x0], v01 = s[y0 * N + x1];
        float v10 = s[y1 * N + x0], v11 = s[y1 * N + x1];
        float tp = v00 + fx * (v01 - v00);
        float bt = v10 + fx * (v11 - v10);
        d[idx] = tp + fy * (bt - tp);
    }
}

__device__ void blur_plane(const float* s, float* d, int N, int ks,
                           int tid, int nt) {
    float g[9];
    float sg = 0.3f * ((ks - 1) * 0.5f - 1.f) + 0.8f;
    float inv2s2 = 1.f / (2.f * sg * sg);
    float sum = 0.f;
    for (int i = 0; i < ks; i++) {
        float dd = (float)i - (ks - 1) * 0.5f;
        g[i] = expf(-dd * dd * inv2s2);
        sum += g[i];
    }
    float inv = 1.f / sum;
    for (int i = 0; i < ks; i++) g[i] *= inv;

    int P = ks / 2;
    const int total = N * N;
    for (int idx = tid; idx < total; idx += nt) {
        int w = idx % N, h = idx / N;
        float acc = 0.f;
        for (int dy = 0; dy < ks; dy++) {
            int y = refl101(h + dy - P, N);
            const float* row = s + y * N;
            float r = 0.f;
            for (int dx = 0; dx < ks; dx++)
                r += g[dx] * row[refl101(w + dx - P, N)];
            acc += g[dy] * r;
        }
        d[idx] = acc;
    }
}

// ---------------------------------------------------------------------------
// prep v2: block = (plane, sigma), 512 threads. First stage computes the
// 80-level from the L2-resident 160-level plane (replacing the former
// standalone 160->80 pyrdown launch), then small pyramid + blur + up-chain
// in static smem; writes the 80-level filter result.
// ---------------------------------------------------------------------------
__global__ void __launch_bounds__(512)
prep_kernel(const float* __restrict__ p3, float* __restrict__ t80) {
    __shared__ float s80[6400];
    __shared__ float s40[1600];
    __shared__ float s20[400];
    __shared__ float s10[100];
    __shared__ float s5[25];
    __shared__ float A[1600];
    __shared__ float B[1600];

    int p = blockIdx.x;
    int sg = blockIdx.y;
    int tid = threadIdx.x, nt = blockDim.x;

    // 160 -> 80 from gmem (L2-hot; 160 level is only 2.5 MB)
    pyrdown_plane(p3 + (size_t)p * 25600, s80, 160, tid, nt);
    __syncthreads();

    pyrdown_plane(s80, s40, 80, tid, nt);
    __syncthreads();
    if (sg >= 1) {
        pyrdown_plane(s40, s20, 40, tid, nt);
        __syncthreads();
        pyrdown_plane(s20, s10, 20, tid, nt);
        __syncthreads();
    }
    if (sg == 2) {
        pyrdown_plane(s10, s5, 10, tid, nt);
        __syncthreads();
    }

    float* T = t80 + ((size_t)sg * NPLANES + p) * 6400;

    if (sg == 0) {
        blur_plane(s40, A, 40, 7, tid, nt); __syncthreads();
        up2_plane(A, T, 40, tid, nt);
    } else if (sg == 1) {
        blur_plane(s10, A, 10, 9, tid, nt); __syncthreads();
        up2_plane(A, B, 10, tid, nt); __syncthreads();
        up2_plane(B, A, 20, tid, nt); __syncthreads();
        up2_plane(A, T, 40, tid, nt);
    } else {
        blur_plane(s5, A, 5, 9, tid, nt); __syncthreads();
        up2_plane(A, B, 5, tid, nt); __syncthreads();
        up2_plane(B, A, 10, tid, nt); __syncthreads();
        up2_plane(A, B, 20, tid, nt); __syncthreads();
        up2_plane(B, T, 40, tid, nt);
    }
}

// ---------------------------------------------------------------------------
// Composed 16-phase, 3-tap polyphase weights (80 -> 320 -> 1280).
// ---------------------------------------------------------------------------
__device__ __constant__ float W16[16][3] = {
    {0.46875f,    0.53125f,   0.f},
    {0.41015625f, 0.5859375f, 0.00390625f},
    {0.35546875f, 0.6328125f, 0.01171875f},
    {0.3046875f,  0.671875f,  0.0234375f},
    {0.2578125f,  0.703125f,  0.0390625f},
    {0.21484375f, 0.7265625f, 0.05859375f},
    {0.17578125f, 0.7421875f, 0.08203125f},
    {0.140625f,   0.75f,      0.109375f},
    {0.109375f,   0.75f,      0.140625f},
    {0.08203125f, 0.7421875f, 0.17578125f},
    {0.05859375f, 0.7265625f, 0.21484375f},
    {0.0390625f,  0.703125f,  0.2578125f},
    {0.0234375f,  0.671875f,  0.3046875f},
    {0.01171875f, 0.6328125f, 0.35546875f},
    {0.00390625f, 0.5859375f, 0.41015625f},
    {0.f,         0.53125f,   0.46875f}
};

// ---------------------------------------------------------------------------
// Composite v2 (proven, R12) + streaming output stores.
// ---------------------------------------------------------------------------
__global__ void __launch_bounds__(256, 3)
composite_kernel(const float* __restrict__ x,
                 const float* __restrict__ t80,
                 float* __restrict__ out) {
    __shared__ float2 SAB[3][4][6];
    __shared__ float  SZ [3][4][6];

    int n   = blockIdx.z;
    int bm0 = blockIdx.y * 8;
    int bq0 = blockIdx.x * 16;
    int tid = threadIdx.x;

    int R0 = (bm0 >> 2) - 1, Q0 = (bq0 >> 2) - 1;
    if (tid < 72) {
        int c = tid / 24;
        int cell = tid - c * 24;
        int i = cell / 6, j = cell - i * 6;
        int gr = min(max(R0 + i, 0), 79);
        int gc = min(max(Q0 + j, 0), 79);
        int off = (n * 3 + c) * 6400 + gr * 80 + gc;
        float f0 = t80[off];
        float f1 = t80[NPLANES * 6400 + off];
        float f2 = t80[2 * NPLANES * 6400 + off];
        SAB[c][i][j] = make_float2(f0, f1);
        SZ[c][i][j] = f2;
    }
    __syncthreads();

    int tx   = tid & 15;
    int th   = tid >> 4;
    int r    = th >> 1;
    int half = th & 1;
    int m = bm0 + r, q = bq0 + tx;
    int lr = r >> 2, lc = tx >> 2;
    int prb = (r & 3) * 4 + half * 2;
    int pcb = (tx & 3) * 4;

    const float EPS = 1e-6f;
    const float LOG10_2 = 0.30102999566398f;
    const float* xb = x + (size_t)n * 3 * H0 * W0;
    float* ob = out + (size_t)n * 3 * H0 * W0;

    ull wxp[4][3];
#pragma unroll
    for (int px = 0; px < 4; px++)
#pragma unroll
        for (int k = 0; k < 3; k++)
            wxp[px][k] = pk2(W16[pcb + px][k], W16[pcb + px][k]);

    float inv_sum[2][4];
#pragma unroll
    for (int j = 0; j < 2; j++) {
        size_t ro = (size_t)(4 * m + half * 2 + j) * W0 + 4 * q;
        float4 x0 = *(const float4*)(xb + ro);
        float4 x1 = *(const float4*)(xb + (size_t)H0 * W0 + ro);
        float4 x2 = *(const float4*)(xb + (size_t)2 * H0 * W0 + ro);
#pragma unroll
        for (int px = 0; px < 4; px++) {
            float s = (((const float*)&x0)[px] + ((const float*)&x1)[px]
                     + ((const float*)&x2)[px]) * 255.f + 3.f;
            inv_sum[j][px] = 2.f / (s + EPS);
        }
    }

#pragma unroll
    for (int c = 0; c < 3; c++) {
        ull  Pab[3][3];
        float Pz[3][3];
#pragma unroll
        for (int a = 0; a < 3; a++)
#pragma unroll
            for (int b = 0; b < 3; b++) {
                float2 v = SAB[c][lr + a][lc + b];
                Pab[a][b] = pk2(v.x, v.y);
                Pz[a][b]  = SZ[c][lr + a][lc + b];
            }

        const float* xc = xb + (size_t)c * H0 * W0;
        float* oc = ob + (size_t)c * H0 * W0;

#pragma unroll
        for (int j = 0; j < 2; j++) {
            int ph = prb + j;
            float wy0 = W16[ph][0], wy1 = W16[ph][1], wy2 = W16[ph][2];
            ull wy0p = pk2(wy0, wy0), wy1p = pk2(wy1, wy1), wy2p = pk2(wy2, wy2);
            ull Rab[3];
            float Rz[3];
#pragma unroll
            for (int b = 0; b < 3; b++) {
                Rab[b] = fma2(Pab[2][b], wy2p,
                         fma2(Pab[1][b], wy1p,
                         mul2(Pab[0][b], wy0p)));
                Rz[b] = wy0 * Pz[0][b] + wy1 * Pz[1][b] + wy2 * Pz[2][b];
            }

            size_t ro = (size_t)(4 * m + half * 2 + j) * W0 + 4 * q;
            float4 xr = *(const float4*)(xc + ro);
            float4 o;
#pragma unroll
            for (int px = 0; px < 4; px++) {
                float wx0 = W16[pcb + px][0], wx1 = W16[pcb + px][1],
                      wx2 = W16[pcb + px][2];
                ull vab = fma2(Rab[2], wxp[px][2],
                          fma2(Rab[1], wxp[px][1],
                          mul2(Rab[0], wxp[px][0])));
                float vz = wx0 * Rz[0] + wx1 * Rz[1] + wx2 * Rz[2];
                float va, vb;
                upk2(vab, va, vb);
                float fa = 255.f * va + 1.f;
                float fb = 255.f * vb + 1.f;
                float fc = 255.f * vz + 1.f;
                float lpv = __log2f((fa + EPS) * (fb + EPS) * (fc + EPS));

                float im = ((const float*)&xr)[px] * 255.f + 1.f;
                float retinex = (__log2f(im + EPS) - lpv * (1.f / 3.f)) * LOG10_2;
                float cr = __log2f(im * inv_sum[j][px] + 1.f) * LOG10_2;
                float e = retinex * cr * 2700.f + 128.f;
                e = fminf(fmaxf(e, 0.f), 255.f);
                ((float*)&o)[px] = e * (1.f / 255.f);
            }
            __stcs((float4*)(oc + ro), o);
        }
    }
}

// ---------------------------------------------------------------------------
// Launch (5 kernels)
// ---------------------------------------------------------------------------
static inline int nblk(long long n, int t) { return (int)((n + t - 1) / t); }

extern "C" void kernel_launch(void* const* d_in, const int* in_sizes, int n_in,
                              void* d_out, int out_size) {
    const float* x = (const float*)d_in[0];
    float* out = (float*)d_out;

    float *p1, *p2, *p3, *t80;
    cudaGetSymbolAddress((void**)&p1, g_pyr1);
    cudaGetSymbolAddress((void**)&p2, g_pyr2);
    cudaGetSymbolAddress((void**)&p3, g_pyr3);
    cudaGetSymbolAddress((void**)&t80, g_t80);

    const int T = 256;
    pyrdown16_kernel<<<nblk((long long)NPLANES * 160 * 160, T), T>>>(x,  p1, 1280, 1280);
    pyrdown16_kernel<<<nblk((long long)NPLANES * 80 * 80,   T), T>>>(p1, p2, 640, 640);
    pyrdown16_kernel<<<nblk((long long)NPLANES * 40 * 40,   T), T>>>(p2, p3, 320, 320);
    prep_kernel<<<dim3(NPLANES, 3), 512>>>(p3, t80);
    composite_kernel<<<dim3(20, 40, 8), 256>>>(x, t80, out);
}

// round 16
// speedup vs baseline: 1.4931x; 1.4931x over previous
#include <cuda_runtime.h>
#include <math.h>

#define NPLANES 24
#define H0 1280
#define W0 1280

// ---------------------------------------------------------------------------
// Scratch
// ---------------------------------------------------------------------------
__device__ float g_pyr1[NPLANES * 640 * 640];
__device__ float g_pyr2[NPLANES * 320 * 320];
__device__ float g_pyr3[NPLANES * 160 * 160];
__device__ float g_pyr4[NPLANES * 80 * 80];
__device__ float g_t80[3 * NPLANES * 80 * 80];   // filter results at 80 level

__device__ __forceinline__ int refl101(int i, int n) {
    if (i < 0) i = -i;
    if (i >= n) i = 2 * n - 2 - i;
    return i;
}

// ---------------------------------------------------------------------------
// f32x2 packed helpers (Blackwell)
// ---------------------------------------------------------------------------
typedef unsigned long long ull;
__device__ __forceinline__ ull pk2(float a, float b) {
    ull r;
    asm("mov.b64 %0, {%1, %2};" : "=l"(r)
        : "r"(__float_as_uint(a)), "r"(__float_as_uint(b)));
    return r;
}
__device__ __forceinline__ void upk2(ull v, float& a, float& b) {
    unsigned int lo, hi;
    asm("mov.b64 {%0, %1}, %2;" : "=r"(lo), "=r"(hi) : "l"(v));
    a = __uint_as_float(lo);
    b = __uint_as_float(hi);
}
__device__ __forceinline__ ull fma2(ull a, ull b, ull c) {
    ull r;
    asm("fma.rn.f32x2 %0, %1, %2, %3;" : "=l"(r) : "l"(a), "l"(b), "l"(c));
    return r;
}
__device__ __forceinline__ ull mul2(ull a, ull b) {
    ull r;
    asm("mul.rn.f32x2 %0, %1, %2;" : "=l"(r) : "l"(a), "l"(b));
    return r;
}

// ---------------------------------------------------------------------------
// pyrDown, 4x4 outputs/thread (proven in R8/R10/R12).
// ---------------------------------------------------------------------------
__global__ void __launch_bounds__(256)
pyrdown16_kernel(const float* __restrict__ src,
                 float* __restrict__ dst, int H, int W) {
    const int Ho = H >> 1, Wo = W >> 1;
    const int Wq = Wo >> 2, Hq = Ho >> 2;
    const int total = NPLANES * Hq * Wq;
    int idx = blockIdx.x * blockDim.x + threadIdx.x;
    if (idx >= total) return;
    int wq = idx % Wq;
    int t  = idx / Wq;
    int hq = t % Hq;
    int p  = t / Hq;
    int ho0 = hq << 2, wo0 = wq << 2;

    const float* s = src + (size_t)p * H * W;
    const float kk[5] = {0.0625f, 0.25f, 0.375f, 0.25f, 0.0625f};
    float* dbase = dst + (size_t)p * Ho * Wo;

    bool interior = (ho0 >= 1) && (2 * ho0 + 8 <= H - 1) &&
                    (wq >= 1) && (8 * wq + 11 <= W - 1);
    if (interior) {
        float hs[11][4];
        const float* rowp = s + (size_t)(2 * ho0 - 2) * W + (8 * wq - 4);
#pragma unroll
        for (int r = 0; r < 11; r++, rowp += W) {
            const float4* r4 = (const float4*)rowp;
            float4 A = r4[0], Bv = r4[1], C = r4[2], D = r4[3];
            float v[16] = {A.x, A.y, A.z, A.w, Bv.x, Bv.y, Bv.z, Bv.w,
                           C.x, C.y, C.z, C.w, D.x, D.y, D.z, D.w};
#pragma unroll
            for (int o = 0; o < 4; o++)
                hs[r][o] = 0.0625f * (v[2 * o + 2] + v[2 * o + 6])
                         + 0.25f   * (v[2 * o + 3] + v[2 * o + 5])
                         + 0.375f  *  v[2 * o + 4];
        }
#pragma unroll
        for (int ry = 0; ry < 4; ry++) {
            float4 o4;
            float* acc = (float*)&o4;
#pragma unroll
            for (int o = 0; o < 4; o++) {
                float a = 0.f;
#pragma unroll
                for (int dy = 0; dy < 5; dy++)
                    a += kk[dy] * hs[2 * ry + dy][o];
                acc[o] = a;
            }
            *(float4*)(dbase + (size_t)(ho0 + ry) * Wo + wo0) = o4;
        }
    } else {
#pragma unroll
        for (int ry = 0; ry < 4; ry++) {
            int ho = ho0 + ry;
            float4 o4;
            float* acc = (float*)&o4;
#pragma unroll
            for (int o = 0; o < 4; o++) {
                int wo = wo0 + o;
                float a = 0.f;
#pragma unroll
                for (int dy = 0; dy < 5; dy++) {
                    int y = refl101(2 * ho + dy - 2, H);
                    const float* row = s + (size_t)y * W;
                    float r2 = 0.f;
#pragma unroll
                    for (int dx = 0; dx < 5; dx++)
                        r2 += kk[dx] * row[refl101(2 * wo + dx - 2, W)];
                    a += kk[dy] * r2;
                }
                acc[o] = a;
            }
            *(float4*)(dbase + (size_t)ho * Wo + wo0) = o4;
        }
    }
}

// ---------------------------------------------------------------------------
// Generic-pointer per-plane helpers (smem or gmem)
// ---------------------------------------------------------------------------
__device__ void pyrdown_plane(const float* s, float* d, int N, int tid, int nt) {
    const int No = N >> 1;
    const int total = No * No;
    const float kk[5] = {0.0625f, 0.25f, 0.375f, 0.25f, 0.0625f};
    for (int idx = tid; idx < total; idx += nt) {
        int wo = idx % No, ho = idx / No;
        float acc = 0.f;
#pragma unroll
        for (int dy = 0; dy < 5; dy++) {
            int y = refl101(2 * ho + dy - 2, N);
            const float* row = s + y * N;
            float r = 0.f;
#pragma unroll
            for (int dx = 0; dx < 5; dx++)
                r += kk[dx] * row[refl101(2 * wo + dx - 2, N)];
            acc += kk[dy] * r;
        }
        d[idx] = acc;
    }
}

__device__ void up2_plane(const float* s, float* d, int N, int tid, int nt) {
    const int No = 2 * N;
    const int total = No * No;
    for (int idx = tid; idx < total; idx += nt) {
        int wo = idx % No, ho = idx / No;
        int iy = (ho >> 1) + (ho & 1) - 1;
        float fy = (ho & 1) ? 0.25f : 0.75f;
        int y0 = max(iy, 0), y1 = min(iy + 1, N - 1);
        int ix = (wo >> 1) + (wo & 1) - 1;
        float fx = (wo & 1) ? 0.25f : 0.75f;
        int x0 = max(ix, 0), x1 = min(ix + 1, N - 1);
        float v00 = s[y0 * N + x0], v01 = s[y0 * N + x1];
        float v10 = s[y1 * N + x0], v11 = s[y1 * N + x1];
        float tp = v00 + fx * (v01 - v00);
        float bt = v10 + fx * (v11 - v10);
        d[idx] = tp + fy * (bt - tp);
    }
}

__device__ void blur_plane(const float* s, float* d, int N, int ks,
                           int tid, int nt) {
    float g[9];
    float sg = 0.3f * ((ks - 1) * 0.5f - 1.f) + 0.8f;
    float inv2s2 = 1.f / (2.f * sg * sg);
    float sum = 0.f;
    for (int i = 0; i < ks; i++) {
        float dd = (float)i - (ks - 1) * 0.5f;
        g[i] = expf(-dd * dd * inv2s2);
        sum += g[i];
    }
    float inv = 1.f / sum;
    for (int i = 0; i < ks; i++) g[i] *= inv;

    int P = ks / 2;
    const int total = N * N;
    for (int idx = tid; idx < total; idx += nt) {
        int w = idx % N, h = idx / N;
        float acc = 0.f;
        for (int dy = 0; dy < ks; dy++) {
            int y = refl101(h + dy - P, N);
            const float* row = s + y * N;
            float r = 0.f;
            for (int dx = 0; dx < ks; dx++)
                r += g[dx] * row[refl101(w + dx - P, N)];
            acc += g[dy] * r;
        }
        d[idx] = acc;
    }
}

// ---------------------------------------------------------------------------
// prep (R12, proven): block = (plane, sigma). 80-level plane in static smem,
// small pyramid + blur + up-chain in smem, write 80-level filter result.
// ---------------------------------------------------------------------------
__global__ void __launch_bounds__(256)
prep_kernel(const float* __restrict__ p4, float* __restrict__ t80) {
    __shared__ float s80[6400];
    __shared__ float s40[1600];
    __shared__ float s20[400];
    __shared__ float s10[100];
    __shared__ float s5[25];
    __shared__ float A[1600];
    __shared__ float B[1600];

    int p = blockIdx.x;
    int sg = blockIdx.y;
    int tid = threadIdx.x, nt = blockDim.x;

    const float4* src4 = (const float4*)(p4 + (size_t)p * 6400);
    for (int i = tid; i < 1600; i += nt)
        ((float4*)s80)[i] = src4[i];
    __syncthreads();

    pyrdown_plane(s80, s40, 80, tid, nt);
    __syncthreads();
    if (sg >= 1) {
        pyrdown_plane(s40, s20, 40, tid, nt);
        __syncthreads();
        pyrdown_plane(s20, s10, 20, tid, nt);
        __syncthreads();
    }
    if (sg == 2) {
        pyrdown_plane(s10, s5, 10, tid, nt);
        __syncthreads();
    }

    float* T = t80 + ((size_t)sg * NPLANES + p) * 6400;

    if (sg == 0) {
        blur_plane(s40, A, 40, 7, tid, nt); __syncthreads();
        up2_plane(A, T, 40, tid, nt);
    } else if (sg == 1) {
        blur_plane(s10, A, 10, 9, tid, nt); __syncthreads();
        up2_plane(A, B, 10, tid, nt); __syncthreads();
        up2_plane(B, A, 20, tid, nt); __syncthreads();
        up2_plane(A, T, 40, tid, nt);
    } else {
        blur_plane(s5, A, 5, 9, tid, nt); __syncthreads();
        up2_plane(A, B, 5, tid, nt); __syncthreads();
        up2_plane(B, A, 10, tid, nt); __syncthreads();
        up2_plane(A, B, 20, tid, nt); __syncthreads();
        up2_plane(B, T, 40, tid, nt);
    }
}

// ---------------------------------------------------------------------------
// Composed 16-phase, 3-tap polyphase weights (80 -> 320 -> 1280).
// ---------------------------------------------------------------------------
__device__ __constant__ float W16[16][3] = {
    {0.46875f,    0.53125f,   0.f},
    {0.41015625f, 0.5859375f, 0.00390625f},
    {0.35546875f, 0.6328125f, 0.01171875f},
    {0.3046875f,  0.671875f,  0.0234375f},
    {0.2578125f,  0.703125f,  0.0390625f},
    {0.21484375f, 0.7265625f, 0.05859375f},
    {0.17578125f, 0.7421875f, 0.08203125f},
    {0.140625f,   0.75f,      0.109375f},
    {0.109375f,   0.75f,      0.140625f},
    {0.08203125f, 0.7421875f, 0.17578125f},
    {0.05859375f, 0.7265625f, 0.21484375f},
    {0.0390625f,  0.703125f,  0.2578125f},
    {0.0234375f,  0.671875f,  0.3046875f},
    {0.01171875f, 0.6328125f, 0.35546875f},
    {0.00390625f, 0.5859375f, 0.41015625f},
    {0.f,         0.53125f,   0.46875f}
};

// ---------------------------------------------------------------------------
// Composite v2 (R12, proven) + hoisted packed wy weights (identical math,
// fewer MOV64s on an issue-bound kernel). Normal (L2-cached) stores.
// ---------------------------------------------------------------------------
__global__ void __launch_bounds__(256, 3)
composite_kernel(const float* __restrict__ x,
                 const float* __restrict__ t80,
                 float* __restrict__ out) {
    __shared__ float2 SAB[3][4][6];
    __shared__ float  SZ [3][4][6];

    int n   = blockIdx.z;
    int bm0 = blockIdx.y * 8;
    int bq0 = blockIdx.x * 16;
    int tid = threadIdx.x;

    int R0 = (bm0 >> 2) - 1, Q0 = (bq0 >> 2) - 1;
    if (tid < 72) {
        int c = tid / 24;
        int cell = tid - c * 24;
        int i = cell / 6, j = cell - i * 6;
        int gr = min(max(R0 + i, 0), 79);
        int gc = min(max(Q0 + j, 0), 79);
        int off = (n * 3 + c) * 6400 + gr * 80 + gc;
        float f0 = t80[off];
        float f1 = t80[NPLANES * 6400 + off];
        float f2 = t80[2 * NPLANES * 6400 + off];
        SAB[c][i][j] = make_float2(f0, f1);
        SZ[c][i][j] = f2;
    }
    __syncthreads();

    int tx   = tid & 15;
    int th   = tid >> 4;
    int r    = th >> 1;
    int half = th & 1;
    int m = bm0 + r, q = bq0 + tx;
    int lr = r >> 2, lc = tx >> 2;
    int prb = (r & 3) * 4 + half * 2;
    int pcb = (tx & 3) * 4;

    const float EPS = 1e-6f;
    const float LOG10_2 = 0.30102999566398f;
    const float* xb = x + (size_t)n * 3 * H0 * W0;
    float* ob = out + (size_t)n * 3 * H0 * W0;

    // hoisted packed px weights (reused across channels and rows)
    ull wxp[4][3];
#pragma unroll
    for (int px = 0; px < 4; px++)
#pragma unroll
        for (int k = 0; k < 3; k++)
            wxp[px][k] = pk2(W16[pcb + px][k], W16[pcb + px][k]);

    // hoisted packed row weights for this thread's 2 phases
    ull wyp[2][3];
    float wys[2][3];
#pragma unroll
    for (int j = 0; j < 2; j++)
#pragma unroll
        for (int k = 0; k < 3; k++) {
            float w = W16[prb + j][k];
            wys[j][k] = w;
            wyp[j][k] = pk2(w, w);
        }

    float inv_sum[2][4];
#pragma unroll
    for (int j = 0; j < 2; j++) {
        size_t ro = (size_t)(4 * m + half * 2 + j) * W0 + 4 * q;
        float4 x0 = *(const float4*)(xb + ro);
        float4 x1 = *(const float4*)(xb + (size_t)H0 * W0 + ro);
        float4 x2 = *(const float4*)(xb + (size_t)2 * H0 * W0 + ro);
#pragma unroll
        for (int px = 0; px < 4; px++) {
            float s = (((const float*)&x0)[px] + ((const float*)&x1)[px]
                     + ((const float*)&x2)[px]) * 255.f + 3.f;
            inv_sum[j][px] = 2.f / (s + EPS);
        }
    }

#pragma unroll
    for (int c = 0; c < 3; c++) {
        ull  Pab[3][3];
        float Pz[3][3];
#pragma unroll
        for (int a = 0; a < 3; a++)
#pragma unroll
            for (int b = 0; b < 3; b++) {
                float2 v = SAB[c][lr + a][lc + b];
                Pab[a][b] = pk2(v.x, v.y);
                Pz[a][b]  = SZ[c][lr + a][lc + b];
            }

        const float* xc = xb + (size_t)c * H0 * W0;
        float* oc = ob + (size_t)c * H0 * W0;

#pragma unroll
        for (int j = 0; j < 2; j++) {
            ull Rab[3];
            float Rz[3];
#pragma unroll
            for (int b = 0; b < 3; b++) {
                Rab[b] = fma2(Pab[2][b], wyp[j][2],
                         fma2(Pab[1][b], wyp[j][1],
                         mul2(Pab[0][b], wyp[j][0])));
                Rz[b] = wys[j][0] * Pz[0][b] + wys[j][1] * Pz[1][b]
                      + wys[j][2] * Pz[2][b];
            }

            size_t ro = (size_t)(4 * m + half * 2 + j) * W0 + 4 * q;
            float4 xr = *(const float4*)(xc + ro);
            float4 o;
#pragma unroll
            for (int px = 0; px < 4; px++) {
                float wx0 = W16[pcb + px][0], wx1 = W16[pcb + px][1],
                      wx2 = W16[pcb + px][2];
                ull vab = fma2(Rab[2], wxp[px][2],
                          fma2(Rab[1], wxp[px][1],
                          mul2(Rab[0], wxp[px][0])));
                float vz = wx0 * Rz[0] + wx1 * Rz[1] + wx2 * Rz[2];
                float va, vb;
                upk2(vab, va, vb);
                float fa = 255.f * va + 1.f;
                float fb = 255.f * vb + 1.f;
                float fc = 255.f * vz + 1.f;
                float lpv = __log2f((fa + EPS) * (fb + EPS) * (fc + EPS));

                float im = ((const float*)&xr)[px] * 255.f + 1.f;
                float retinex = (__log2f(im + EPS) - lpv * (1.f / 3.f)) * LOG10_2;
                float cr = __log2f(im * inv_sum[j][px] + 1.f) * LOG10_2;
                float e = retinex * cr * 2700.f + 128.f;
                e = fminf(fmaxf(e, 0.f), 255.f);
                ((float*)&o)[px] = e * (1.f / 255.f);
            }
            *(float4*)(oc + ro) = o;
        }
    }
}

// ---------------------------------------------------------------------------
// Launch (6 kernels — R12 structure)
// ---------------------------------------------------------------------------
static inline int nblk(long long n, int t) { return (int)((n + t - 1) / t); }

extern "C" void kernel_launch(void* const* d_in, const int* in_sizes, int n_in,
                              void* d_out, int out_size) {
    const float* x = (const float*)d_in[0];
    float* out = (float*)d_out;

    float *p1, *p2, *p3, *p4, *t80;
    cudaGetSymbolAddress((void**)&p1, g_pyr1);
    cudaGetSymbolAddress((void**)&p2, g_pyr2);
    cudaGetSymbolAddress((void**)&p3, g_pyr3);
    cudaGetSymbolAddress((void**)&p4, g_pyr4);
    cudaGetSymbolAddress((void**)&t80, g_t80);

    const int T = 256;
    pyrdown16_kernel<<<nblk((long long)NPLANES * 160 * 160, T), T>>>(x,  p1, 1280, 1280);
    pyrdown16_kernel<<<nblk((long long)NPLANES * 80 * 80,   T), T>>>(p1, p2, 640, 640);
    pyrdown16_kernel<<<nblk((long long)NPLANES * 40 * 40,   T), T>>>(p2, p3, 320, 320);
    pyrdown16_kernel<<<nblk((long long)NPLANES * 20 * 20,   T), T>>>(p3, p4, 160, 160);
    prep_kernel<<<dim3(NPLANES, 3), 256>>>(p4, t80);
    composite_kernel<<<dim3(20, 40, 8), 256>>>(x, t80, out);
}

// round 17
// speedup vs baseline: 1.5366x; 1.0291x over previous
#include <cuda_runtime.h>
#include <math.h>

#define NPLANES 24
#define H0 1280
#define W0 1280

// ---------------------------------------------------------------------------
// Scratch
// ---------------------------------------------------------------------------
__device__ float g_pyr1[NPLANES * 640 * 640];
__device__ float g_pyr2[NPLANES * 320 * 320];
__device__ float g_pyr3[NPLANES * 160 * 160];
__device__ float g_pyr4[NPLANES * 80 * 80];
__device__ float g_t80[3 * NPLANES * 80 * 80];   // filter results at 80 level

__device__ __forceinline__ int refl101(int i, int n) {
    if (i < 0) i = -i;
    if (i >= n) i = 2 * n - 2 - i;
    return i;
}

// ---------------------------------------------------------------------------
// f32x2 packed helpers (Blackwell)
// ---------------------------------------------------------------------------
typedef unsigned long long ull;
__device__ __forceinline__ ull pk2(float a, float b) {
    ull r;
    asm("mov.b64 %0, {%1, %2};" : "=l"(r)
        : "r"(__float_as_uint(a)), "r"(__float_as_uint(b)));
    return r;
}
__device__ __forceinline__ void upk2(ull v, float& a, float& b) {
    unsigned int lo, hi;
    asm("mov.b64 {%0, %1}, %2;" : "=r"(lo), "=r"(hi) : "l"(v));
    a = __uint_as_float(lo);
    b = __uint_as_float(hi);
}
__device__ __forceinline__ ull fma2(ull a, ull b, ull c) {
    ull r;
    asm("fma.rn.f32x2 %0, %1, %2, %3;" : "=l"(r) : "l"(a), "l"(b), "l"(c));
    return r;
}
__device__ __forceinline__ ull mul2(ull a, ull b) {
    ull r;
    asm("mul.rn.f32x2 %0, %1, %2;" : "=l"(r) : "l"(a), "l"(b));
    return r;
}

// ---------------------------------------------------------------------------
// pyrDown, 4x4 outputs/thread — big levels (plenty of blocks).
// ---------------------------------------------------------------------------
__global__ void __launch_bounds__(256)
pyrdown16_kernel(const float* __restrict__ src,
                 float* __restrict__ dst, int H, int W) {
    const int Ho = H >> 1, Wo = W >> 1;
    const int Wq = Wo >> 2, Hq = Ho >> 2;
    const int total = NPLANES * Hq * Wq;
    int idx = blockIdx.x * blockDim.x + threadIdx.x;
    if (idx >= total) return;
    int wq = idx % Wq;
    int t  = idx / Wq;
    int hq = t % Hq;
    int p  = t / Hq;
    int ho0 = hq << 2, wo0 = wq << 2;

    const float* s = src + (size_t)p * H * W;
    const float kk[5] = {0.0625f, 0.25f, 0.375f, 0.25f, 0.0625f};
    float* dbase = dst + (size_t)p * Ho * Wo;

    bool interior = (ho0 >= 1) && (2 * ho0 + 8 <= H - 1) &&
                    (wq >= 1) && (8 * wq + 11 <= W - 1);
    if (interior) {
        float hs[11][4];
        const float* rowp = s + (size_t)(2 * ho0 - 2) * W + (8 * wq - 4);
#pragma unroll
        for (int r = 0; r < 11; r++, rowp += W) {
            const float4* r4 = (const float4*)rowp;
            float4 A = r4[0], Bv = r4[1], C = r4[2], D = r4[3];
            float v[16] = {A.x, A.y, A.z, A.w, Bv.x, Bv.y, Bv.z, Bv.w,
                           C.x, C.y, C.z, C.w, D.x, D.y, D.z, D.w};
#pragma unroll
            for (int o = 0; o < 4; o++)
                hs[r][o] = 0.0625f * (v[2 * o + 2] + v[2 * o + 6])
                         + 0.25f   * (v[2 * o + 3] + v[2 * o + 5])
                         + 0.375f  *  v[2 * o + 4];
        }
#pragma unroll
        for (int ry = 0; ry < 4; ry++) {
            float4 o4;
            float* acc = (float*)&o4;
#pragma unroll
            for (int o = 0; o < 4; o++) {
                float a = 0.f;
#pragma unroll
                for (int dy = 0; dy < 5; dy++)
                    a += kk[dy] * hs[2 * ry + dy][o];
                acc[o] = a;
            }
            *(float4*)(dbase + (size_t)(ho0 + ry) * Wo + wo0) = o4;
        }
    } else {
#pragma unroll
        for (int ry = 0; ry < 4; ry++) {
            int ho = ho0 + ry;
            float4 o4;
            float* acc = (float*)&o4;
#pragma unroll
            for (int o = 0; o < 4; o++) {
                int wo = wo0 + o;
                float a = 0.f;
#pragma unroll
                for (int dy = 0; dy < 5; dy++) {
                    int y = refl101(2 * ho + dy - 2, H);
                    const float* row = s + (size_t)y * W;
                    float r2 = 0.f;
#pragma unroll
                    for (int dx = 0; dx < 5; dx++)
                        r2 += kk[dx] * row[refl101(2 * wo + dx - 2, W)];
                    a += kk[dy] * r2;
                }
                acc[o] = a;
            }
            *(float4*)(dbase + (size_t)ho * Wo + wo0) = o4;
        }
    }
}

// ---------------------------------------------------------------------------
// pyrDown, 4 outputs/thread — small levels (R6 code, measured 7.4us @160->80).
// ---------------------------------------------------------------------------
__global__ void __launch_bounds__(256)
pyrdown4_kernel(const float* __restrict__ src,
                float* __restrict__ dst, int H, int W) {
    const int Ho = H >> 1, Wo = W >> 1, Wq = Wo >> 2;
    const int total = NPLANES * Ho * Wq;
    int idx = blockIdx.x * blockDim.x + threadIdx.x;
    if (idx >= total) return;
    int wq = idx % Wq;
    int t  = idx / Wq;
    int ho = t % Ho;
    int p  = t / Ho;
    int wo0 = wq << 2;

    const float* s = src + (size_t)p * H * W;
    const float kk[5] = {0.0625f, 0.25f, 0.375f, 0.25f, 0.0625f};
    float acc[4] = {0.f, 0.f, 0.f, 0.f};

    bool interior = (ho >= 1) && (2 * ho + 2 <= H - 1) &&
                    (wq >= 1) && (8 * wq + 11 <= W - 1);
    if (interior) {
        const float* rowp = s + (size_t)(2 * ho - 2) * W + (8 * wq - 4);
#pragma unroll
        for (int dy = 0; dy < 5; dy++, rowp += W) {
            const float4* r4 = (const float4*)rowp;
            float4 A = r4[0], B = r4[1], C = r4[2], D = r4[3];
            float v[16] = {A.x, A.y, A.z, A.w, B.x, B.y, B.z, B.w,
                           C.x, C.y, C.z, C.w, D.x, D.y, D.z, D.w};
            float ky = kk[dy];
#pragma unroll
            for (int o = 0; o < 4; o++) {
                float hs = 0.0625f * (v[2 * o + 2] + v[2 * o + 6])
                         + 0.25f   * (v[2 * o + 3] + v[2 * o + 5])
                         + 0.375f  *  v[2 * o + 4];
                acc[o] += ky * hs;
            }
        }
    } else {
#pragma unroll
        for (int o = 0; o < 4; o++) {
            int wo = wo0 + o;
            float a = 0.f;
#pragma unroll
            for (int dy = 0; dy < 5; dy++) {
                int y = refl101(2 * ho + dy - 2, H);
                const float* row = s + (size_t)y * W;
                float r2 = 0.f;
#pragma unroll
                for (int dx = 0; dx < 5; dx++)
                    r2 += kk[dx] * row[refl101(2 * wo + dx - 2, W)];
                a += kk[dy] * r2;
            }
            acc[o] = a;
        }
    }
    float4* d = (float4*)(dst + (size_t)p * Ho * Wo + (size_t)ho * Wo + wo0);
    *d = make_float4(acc[0], acc[1], acc[2], acc[3]);
}

// ---------------------------------------------------------------------------
// Generic-pointer per-plane helpers (smem or gmem)
// ---------------------------------------------------------------------------
__device__ void pyrdown_plane(const float* s, float* d, int N, int tid, int nt) {
    const int No = N >> 1;
    const int total = No * No;
    const float kk[5] = {0.0625f, 0.25f, 0.375f, 0.25f, 0.0625f};
    for (int idx = tid; idx < total; idx += nt) {
        int wo = idx % No, ho = idx / No;
        float acc = 0.f;
#pragma unroll
        for (int dy = 0; dy < 5; dy++) {
            int y = refl101(2 * ho + dy - 2, N);
            const float* row = s + y * N;
            float r = 0.f;
#pragma unroll
            for (int dx = 0; dx < 5; dx++)
                r += kk[dx] * row[refl101(2 * wo + dx - 2, N)];
            acc += kk[dy] * r;
        }
        d[idx] = acc;
    }
}

__device__ void up2_plane(const float* s, float* d, int N, int tid, int nt) {
    const int No = 2 * N;
    const int total = No * No;
    for (int idx = tid; idx < total; idx += nt) {
        int wo = idx % No, ho = idx / No;
        int iy = (ho >> 1) + (ho & 1) - 1;
        float fy = (ho & 1) ? 0.25f : 0.75f;
        int y0 = max(iy, 0), y1 = min(iy + 1, N - 1);
        int ix = (wo >> 1) + (wo & 1) - 1;
        float fx = (wo & 1) ? 0.25f : 0.75f;
        int x0 = max(ix, 0), x1 = min(ix + 1, N - 1);
        float v00 = s[y0 * N + x0], v01 = s[y0 * N + x1];
        float v10 = s[y1 * N + x0], v11 = s[y1 * N + x1];
        float tp = v00 + fx * (v01 - v00);
        float bt = v10 + fx * (v11 - v10);
        d[idx] = tp + fy * (bt - tp);
    }
}

__device__ void blur_plane(const float* s, float* d, int N, int ks,
                           int tid, int nt) {
    float g[9];
    float sg = 0.3f * ((ks - 1) * 0.5f - 1.f) + 0.8f;
    float inv2s2 = 1.f / (2.f * sg * sg);
    float sum = 0.f;
    for (int i = 0; i < ks; i++) {
        float dd = (float)i - (ks - 1) * 0.5f;
        g[i] = expf(-dd * dd * inv2s2);
        sum += g[i];
    }
    float inv = 1.f / sum;
    for (int i = 0; i < ks; i++) g[i] *= inv;

    int P = ks / 2;
    const int total = N * N;
    for (int idx = tid; idx < total; idx += nt) {
        int w = idx % N, h = idx / N;
        float acc = 0.f;
        for (int dy = 0; dy < ks; dy++) {
            int y = refl101(h + dy - P, N);
            const float* row = s + y * N;
            float r = 0.f;
            for (int dx = 0; dx < ks; dx++)
                r += g[dx] * row[refl101(w + dx - P, N)];
            acc += g[dy] * r;
        }
        d[idx] = acc;
    }
}

// ---------------------------------------------------------------------------
// prep (R12, proven): block = (plane, sigma). 80-level plane in static smem,
// small pyramid + blur + up-chain in smem, write 80-level filter result.
// ---------------------------------------------------------------------------
__global__ void __launch_bounds__(256)
prep_kernel(const float* __restrict__ p4, float* __restrict__ t80) {
    __shared__ float s80[6400];
    __shared__ float s40[1600];
    __shared__ float s20[400];
    __shared__ float s10[100];
    __shared__ float s5[25];
    __shared__ float A[1600];
    __shared__ float B[1600];

    int p = blockIdx.x;
    int sg = blockIdx.y;
    int tid = threadIdx.x, nt = blockDim.x;

    const float4* src4 = (const float4*)(p4 + (size_t)p * 6400);
    for (int i = tid; i < 1600; i += nt)
        ((float4*)s80)[i] = src4[i];
    __syncthreads();

    pyrdown_plane(s80, s40, 80, tid, nt);
    __syncthreads();
    if (sg >= 1) {
        pyrdown_plane(s40, s20, 40, tid, nt);
        __syncthreads();
        pyrdown_plane(s20, s10, 20, tid, nt);
        __syncthreads();
    }
    if (sg == 2) {
        pyrdown_plane(s10, s5, 10, tid, nt);
        __syncthreads();
    }

    float* T = t80 + ((size_t)sg * NPLANES + p) * 6400;

    if (sg == 0) {
        blur_plane(s40, A, 40, 7, tid, nt); __syncthreads();
        up2_plane(A, T, 40, tid, nt);
    } else if (sg == 1) {
        blur_plane(s10, A, 10, 9, tid, nt); __syncthreads();
        up2_plane(A, B, 10, tid, nt); __syncthreads();
        up2_plane(B, A, 20, tid, nt); __syncthreads();
        up2_plane(A, T, 40, tid, nt);
    } else {
        blur_plane(s5, A, 5, 9, tid, nt); __syncthreads();
        up2_plane(A, B, 5, tid, nt); __syncthreads();
        up2_plane(B, A, 10, tid, nt); __syncthreads();
        up2_plane(A, B, 20, tid, nt); __syncthreads();
        up2_plane(B, T, 40, tid, nt);
    }
}

// ---------------------------------------------------------------------------
// Composed 16-phase, 3-tap polyphase weights (80 -> 320 -> 1280).
// ---------------------------------------------------------------------------
__device__ __constant__ float W16[16][3] = {
    {0.46875f,    0.53125f,   0.f},
    {0.41015625f, 0.5859375f, 0.00390625f},
    {0.35546875f, 0.6328125f, 0.01171875f},
    {0.3046875f,  0.671875f,  0.0234375f},
    {0.2578125f,  0.703125f,  0.0390625f},
    {0.21484375f, 0.7265625f, 0.05859375f},
    {0.17578125f, 0.7421875f, 0.08203125f},
    {0.140625f,   0.75f,      0.109375f},
    {0.109375f,   0.75f,      0.140625f},
    {0.08203125f, 0.7421875f, 0.17578125f},
    {0.05859375f, 0.7265625f, 0.21484375f},
    {0.0390625f,  0.703125f,  0.2578125f},
    {0.0234375f,  0.671875f,  0.3046875f},
    {0.01171875f, 0.6328125f, 0.35546875f},
    {0.00390625f, 0.5859375f, 0.41015625f},
    {0.f,         0.53125f,   0.46875f}
};

// ---------------------------------------------------------------------------
// Composite v2 (proven): 256 thr/block, thread = half a 320-cell.
// ---------------------------------------------------------------------------
__global__ void __launch_bounds__(256, 3)
composite_kernel(const float* __restrict__ x,
                 const float* __restrict__ t80,
                 float* __restrict__ out) {
    __shared__ float2 SAB[3][4][6];
    __shared__ float  SZ [3][4][6];

    int n   = blockIdx.z;
    int bm0 = blockIdx.y * 8;
    int bq0 = blockIdx.x * 16;
    int tid = threadIdx.x;

    int R0 = (bm0 >> 2) - 1, Q0 = (bq0 >> 2) - 1;
    if (tid < 72) {
        int c = tid / 24;
        int cell = tid - c * 24;
        int i = cell / 6, j = cell - i * 6;
        int gr = min(max(R0 + i, 0), 79);
        int gc = min(max(Q0 + j, 0), 79);
        int off = (n * 3 + c) * 6400 + gr * 80 + gc;
        float f0 = t80[off];
        float f1 = t80[NPLANES * 6400 + off];
        float f2 = t80[2 * NPLANES * 6400 + off];
        SAB[c][i][j] = make_float2(f0, f1);
        SZ[c][i][j] = f2;
    }
    __syncthreads();

    int tx   = tid & 15;
    int th   = tid >> 4;
    int r    = th >> 1;
    int half = th & 1;
    int m = bm0 + r, q = bq0 + tx;
    int lr = r >> 2, lc = tx >> 2;
    int prb = (r & 3) * 4 + half * 2;
    int pcb = (tx & 3) * 4;

    const float EPS = 1e-6f;
    const float LOG10_2 = 0.30102999566398f;
    const float* xb = x + (size_t)n * 3 * H0 * W0;
    float* ob = out + (size_t)n * 3 * H0 * W0;

    ull wxp[4][3];
#pragma unroll
    for (int px = 0; px < 4; px++)
#pragma unroll
        for (int k = 0; k < 3; k++)
            wxp[px][k] = pk2(W16[pcb + px][k], W16[pcb + px][k]);

    ull wyp[2][3];
    float wys[2][3];
#pragma unroll
    for (int j = 0; j < 2; j++)
#pragma unroll
        for (int k = 0; k < 3; k++) {
            float w = W16[prb + j][k];
            wys[j][k] = w;
            wyp[j][k] = pk2(w, w);
        }

    float inv_sum[2][4];
#pragma unroll
    for (int j = 0; j < 2; j++) {
        size_t ro = (size_t)(4 * m + half * 2 + j) * W0 + 4 * q;
        float4 x0 = *(const float4*)(xb + ro);
        float4 x1 = *(const float4*)(xb + (size_t)H0 * W0 + ro);
        float4 x2 = *(const float4*)(xb + (size_t)2 * H0 * W0 + ro);
#pragma unroll
        for (int px = 0; px < 4; px++) {
            float s = (((const float*)&x0)[px] + ((const float*)&x1)[px]
                     + ((const float*)&x2)[px]) * 255.f + 3.f;
            inv_sum[j][px] = 2.f / (s + EPS);
        }
    }

#pragma unroll
    for (int c = 0; c < 3; c++) {
        ull  Pab[3][3];
        float Pz[3][3];
#pragma unroll
        for (int a = 0; a < 3; a++)
#pragma unroll
            for (int b = 0; b < 3; b++) {
                float2 v = SAB[c][lr + a][lc + b];
                Pab[a][b] = pk2(v.x, v.y);
                Pz[a][b]  = SZ[c][lr + a][lc + b];
            }

        const float* xc = xb + (size_t)c * H0 * W0;
        float* oc = ob + (size_t)c * H0 * W0;

#pragma unroll
        for (int j = 0; j < 2; j++) {
            ull Rab[3];
            float Rz[3];
#pragma unroll
            for (int b = 0; b < 3; b++) {
                Rab[b] = fma2(Pab[2][b], wyp[j][2],
                         fma2(Pab[1][b], wyp[j][1],
                         mul2(Pab[0][b], wyp[j][0])));
                Rz[b] = wys[j][0] * Pz[0][b] + wys[j][1] * Pz[1][b]
                      + wys[j][2] * Pz[2][b];
            }

            size_t ro = (size_t)(4 * m + half * 2 + j) * W0 + 4 * q;
            float4 xr = *(const float4*)(xc + ro);
            float4 o;
#pragma unroll
            for (int px = 0; px < 4; px++) {
                float wx0 = W16[pcb + px][0], wx1 = W16[pcb + px][1],
                      wx2 = W16[pcb + px][2];
                ull vab = fma2(Rab[2], wxp[px][2],
                          fma2(Rab[1], wxp[px][1],
                          mul2(Rab[0], wxp[px][0])));
                float vz = wx0 * Rz[0] + wx1 * Rz[1] + wx2 * Rz[2];
                float va, vb;
                upk2(vab, va, vb);
                float fa = 255.f * va + 1.f;
                float fb = 255.f * vb + 1.f;
                float fc = 255.f * vz + 1.f;
                float lpv = __log2f((fa + EPS) * (fb + EPS) * (fc + EPS));

                float im = ((const float*)&xr)[px] * 255.f + 1.f;
                float retinex = (__log2f(im + EPS) - lpv * (1.f / 3.f)) * LOG10_2;
                float cr = __log2f(im * inv_sum[j][px] + 1.f) * LOG10_2;
                float e = retinex * cr * 2700.f + 128.f;
                e = fminf(fmaxf(e, 0.f), 255.f);
                ((float*)&o)[px] = e * (1.f / 255.f);
            }
            *(float4*)(oc + ro) = o;
        }
    }
}

// ---------------------------------------------------------------------------
// Launch (6 kernels)
// ---------------------------------------------------------------------------
static inline int nblk(long long n, int t) { return (int)((n + t - 1) / t); }

extern "C" void kernel_launch(void* const* d_in, const int* in_sizes, int n_in,
                              void* d_out, int out_size) {
    const float* x = (const float*)d_in[0];
    float* out = (float*)d_out;

    float *p1, *p2, *p3, *p4, *t80;
    cudaGetSymbolAddress((void**)&p1, g_pyr1);
    cudaGetSymbolAddress((void**)&p2, g_pyr2);
    cudaGetSymbolAddress((void**)&p3, g_pyr3);
    cudaGetSymbolAddress((void**)&p4, g_pyr4);
    cudaGetSymbolAddress((void**)&t80, g_t80);

    const int T = 256;
    // big levels: 16 outputs/thread (block-rich already)
    pyrdown16_kernel<<<nblk((long long)NPLANES * 160 * 160, T), T>>>(x,  p1, 1280, 1280);
    pyrdown16_kernel<<<nblk((long long)NPLANES * 80 * 80,   T), T>>>(p1, p2, 640, 640);
    // small levels: 4 outputs/thread (4x more blocks; measured faster)
    pyrdown4_kernel<<<nblk((long long)NPLANES * 160 * 40, T), T>>>(p2, p3, 320, 320);
    pyrdown4_kernel<<<nblk((long long)NPLANES * 80 * 20,  T), T>>>(p3, p4, 160, 160);
    prep_kernel<<<dim3(NPLANES, 3), 256>>>(p4, t80);
    composite_kernel<<<dim3(20, 40, 8), 256>>>(x, t80, out);
}